// round 4
// baseline (speedup 1.0000x reference)
#include <cuda_runtime.h>
#include <cstddef>

#define VOCAB 50000
#define EMBD  128
#define STORY 200
#define SENT  32
#define BATCH 64
#define QLEN  32
#define HOPS  3
#define NLBLK 196   // logits blocks = ceil(50000/256)

// Scratch (device globals — no allocation allowed)
__device__ float g_emb[4 * BATCH * STORY * EMBD];  // 26.2 MB: emb[k][b][s][e]
__device__ float g_u[BATCH * EMBD];
__device__ float g_lse[BATCH];
__device__ float g_pm[BATCH * 256];   // per-(batch, logits-block) partial max
__device__ float g_ps[BATCH * 256];   // per-(batch, logits-block) partial sum

// ---------------------------------------------------------------------------
// Kernel 1: embedding gather-sums (L2-roofline bound; unchanged).
// ---------------------------------------------------------------------------
__global__ void embed_kernel(const float* __restrict__ A,
                             const int* __restrict__ x,
                             const int* __restrict__ q) {
    const int NEMB = 4 * BATCH * STORY;  // 51200
    int w    = threadIdx.x >> 5;
    int lane = threadIdx.x & 31;
    int row  = blockIdx.x * 8 + w;

    __shared__ int toks[8][SENT];

    const int*   tokptr;
    const float* table;
    float*       out;

    if (row < NEMB) {
        int k   = row / (BATCH * STORY);
        int rem = row % (BATCH * STORY);
        tokptr = x + rem * SENT;
        table  = A + (size_t)k * VOCAB * EMBD;
        out    = g_emb + (size_t)row * EMBD;
    } else if (row < NEMB + BATCH) {
        int b  = row - NEMB;
        tokptr = q + b * QLEN;
        table  = A + (size_t)1 * VOCAB * EMBD;
        out    = g_u + b * EMBD;
    } else {
        return;
    }

    toks[w][lane] = tokptr[lane];
    __syncwarp();

    float4 acc = make_float4(0.f, 0.f, 0.f, 0.f);
#pragma unroll 8
    for (int t = 0; t < SENT; t++) {
        const float4* r = (const float4*)(table + (size_t)toks[w][t] * EMBD);
        float4 v = __ldg(&r[lane]);
        acc.x += v.x; acc.y += v.y; acc.z += v.z; acc.w += v.w;
    }
    ((float4*)out)[lane] = acc;
}

// ---------------------------------------------------------------------------
// Kernel 2: 3 attention hops (unchanged).
// ---------------------------------------------------------------------------
__global__ void hops_kernel(const float* __restrict__ TA,
                            const float* __restrict__ TC) {
    int b   = blockIdx.x;
    int tid = threadIdx.x;
    int warp = tid >> 5, lane = tid & 31;

    __shared__ float su[EMBD];
    __shared__ float sc[STORY];
    __shared__ float wsum[2][EMBD];
    __shared__ float sred[8];
    __shared__ float s_scalar[4];

    if (tid < EMBD) su[tid] = g_u[b * EMBD + tid];
    __syncthreads();

    for (int k = 0; k < HOPS; k++) {
        if (tid < EMBD) {
            float v = su[tid];
            for (int o = 16; o > 0; o >>= 1) v += __shfl_down_sync(0xffffffffu, v, o);
            if (lane == 0) sred[warp] = v;
        }
        __syncthreads();
        if (tid == 0) s_scalar[0] = sred[0] + sred[1] + sred[2] + sred[3];
        __syncthreads();
        float sum_u = s_scalar[0];

        float4 uv = ((const float4*)su)[lane];
        const float4* embk = (const float4*)(g_emb +
            ((size_t)k * BATCH * STORY + (size_t)b * STORY) * EMBD);
        for (int s = warp; s < STORY; s += 8) {
            float4 m4 = embk[s * 32 + lane];
            float d = m4.x * uv.x + m4.y * uv.y + m4.z * uv.z + m4.w * uv.w;
            for (int o = 16; o > 0; o >>= 1) d += __shfl_down_sync(0xffffffffu, d, o);
            if (lane == 0) sc[s] = d + TA[s] * sum_u;
        }
        __syncthreads();

        if (warp == 0) {
            float m = -1e30f;
            for (int s = lane; s < STORY; s += 32) m = fmaxf(m, sc[s]);
            for (int o = 16; o > 0; o >>= 1) m = fmaxf(m, __shfl_down_sync(0xffffffffu, m, o));
            if (lane == 0) s_scalar[1] = m;
        }
        __syncthreads();
        float smax = s_scalar[1];
        if (tid < STORY) sc[tid] = __expf(sc[tid] - smax);
        __syncthreads();
        if (warp == 0) {
            float sm = 0.f, td = 0.f;
            for (int s = lane; s < STORY; s += 32) { sm += sc[s]; td += sc[s] * TC[s]; }
            for (int o = 16; o > 0; o >>= 1) {
                sm += __shfl_down_sync(0xffffffffu, sm, o);
                td += __shfl_down_sync(0xffffffffu, td, o);
            }
            if (lane == 0) { s_scalar[2] = sm; s_scalar[3] = td; }
        }
        __syncthreads();

        int e = tid & 127, part = tid >> 7;
        const float* embc = g_emb +
            ((size_t)(k + 1) * BATCH * STORY + (size_t)b * STORY) * EMBD;
        float acc = 0.f;
        int s0 = part * 100;
#pragma unroll 4
        for (int s = s0; s < s0 + 100; s++) acc += embc[s * EMBD + e] * sc[s];
        wsum[part][e] = acc;
        __syncthreads();
        if (tid < EMBD) {
            float inv = 1.0f / s_scalar[2];
            su[tid] = su[tid] + (wsum[0][tid] + wsum[1][tid] + s_scalar[3]) * inv;
        }
        __syncthreads();
    }
    if (tid < EMBD) g_u[b * EMBD + tid] = su[tid];
}

// ---------------------------------------------------------------------------
// Kernel 3: logits (packed fma.rn.f32x2, broadcast-u) + fused LSE partials.
// ---------------------------------------------------------------------------
__device__ __forceinline__ unsigned long long fma2(unsigned long long a,
                                                   unsigned long long b,
                                                   unsigned long long c) {
    unsigned long long d;
    asm("fma.rn.f32x2 %0, %1, %2, %3;" : "=l"(d) : "l"(a), "l"(b), "l"(c));
    return d;
}
__device__ __forceinline__ unsigned long long pack2(float x) {
    unsigned long long d;
    asm("mov.b64 %0, {%1, %1};" : "=l"(d) : "f"(x));
    return d;
}
__device__ __forceinline__ float lo32(unsigned long long a) {
    return __uint_as_float((unsigned)(a & 0xffffffffull));
}
__device__ __forceinline__ float hi32(unsigned long long a) {
    return __uint_as_float((unsigned)(a >> 32));
}

__global__ void __launch_bounds__(256) logits_kernel(const float* __restrict__ A,
                                                     float* __restrict__ out) {
    const float* A3 = A + (size_t)HOPS * VOCAB * EMBD;

    __shared__ float2 up2[32 * EMBD];   // 32 KB
    __shared__ float  As[8 * 256];      // 8 KB
    __shared__ float  red_m[8][32];     // per-warp per-batch partial max
    __shared__ float  red_s[8][32];     // per-warp per-batch partial sum

    int tid = threadIdx.x;
    for (int i = tid; i < 32 * EMBD; i += 256) {
        int p = i >> 7, e = i & 127;
        up2[p * EMBD + e] = make_float2(g_u[(2 * p) * EMBD + e],
                                        g_u[(2 * p + 1) * EMBD + e]);
    }

    int vp = tid & 127;
    int bg = tid >> 7;
    int warp = tid >> 5, lane = tid & 31;
    int vbase = blockIdx.x * 256;

    unsigned long long acc0[16], acc1[16];
#pragma unroll
    for (int j = 0; j < 16; j++) { acc0[j] = 0ull; acc1[j] = 0ull; }

    const unsigned long long* uq =
        (const unsigned long long*)up2 + (size_t)bg * 16 * EMBD;

    for (int c = 0; c < 16; c++) {   // 16 chunks of 8 e
        __syncthreads();
#pragma unroll
        for (int i = 0; i < 2; i++) {
            int f   = tid + i * 256;
            int vl2 = f >> 1;
            int e4  = f & 1;
            int vr  = min(vbase + vl2, VOCAB - 1);
            float4 val = __ldg((const float4*)A3 + (size_t)vr * 32 + c * 2 + e4);
            int eb = e4 * 4;
            As[(eb + 0) * 256 + vl2] = val.x;
            As[(eb + 1) * 256 + vl2] = val.y;
            As[(eb + 2) * 256 + vl2] = val.z;
            As[(eb + 3) * 256 + vl2] = val.w;
        }
        __syncthreads();

#pragma unroll
        for (int e = 0; e < 8; e++) {
            float2 a01 = ((const float2*)(As + e * 256))[vp];
            unsigned long long a0 = pack2(a01.x);
            unsigned long long a1 = pack2(a01.y);
            int ue = c * 8 + e;
#pragma unroll
            for (int j = 0; j < 16; j++) {
                unsigned long long uu = uq[j * EMBD + ue];  // warp-uniform broadcast
                acc0[j] = fma2(a0, uu, acc0[j]);
                acc1[j] = fma2(a1, uu, acc1[j]);
            }
        }
    }

    int v0 = vbase + 2 * vp;
    bool ok0 = (v0 < VOCAB);
    bool ok1 = (v0 + 1 < VOCAB);

    // store raw logits
    if (ok0) {
#pragma unroll
        for (int j = 0; j < 16; j++) {
            int b = bg * 32 + 2 * j;
            float2 r0 = make_float2(lo32(acc0[j]), lo32(acc1[j]));
            float2 r1 = make_float2(hi32(acc0[j]), hi32(acc1[j]));
            *(float2*)(out + (size_t)b * VOCAB + v0)       = r0;
            *(float2*)(out + (size_t)(b + 1) * VOCAB + v0) = r1;
        }
    }

    // ---- fused LSE partials: per-block per-batch (max, sum-exp) ----
#pragma unroll
    for (int j = 0; j < 16; j++) {
        // batch 2j: values (lo acc0, lo acc1); batch 2j+1: (hi acc0, hi acc1)
        float a0 = lo32(acc0[j]), b0 = lo32(acc1[j]);
        float a1 = hi32(acc0[j]), b1 = hi32(acc1[j]);
        float m0 = fmaxf(ok0 ? a0 : -1e30f, ok1 ? b0 : -1e30f);
        float m1 = fmaxf(ok0 ? a1 : -1e30f, ok1 ? b1 : -1e30f);
        float s0 = (ok0 ? __expf(a0 - m0) : 0.f) + (ok1 ? __expf(b0 - m0) : 0.f);
        float s1 = (ok0 ? __expf(a1 - m1) : 0.f) + (ok1 ? __expf(b1 - m1) : 0.f);
#pragma unroll
        for (int o = 16; o > 0; o >>= 1) {
            float mo0 = __shfl_down_sync(0xffffffffu, m0, o);
            float so0 = __shfl_down_sync(0xffffffffu, s0, o);
            float mo1 = __shfl_down_sync(0xffffffffu, m1, o);
            float so1 = __shfl_down_sync(0xffffffffu, s1, o);
            float mn0 = fmaxf(m0, mo0);
            s0 = s0 * __expf(m0 - mn0) + so0 * __expf(mo0 - mn0);
            m0 = mn0;
            float mn1 = fmaxf(m1, mo1);
            s1 = s1 * __expf(m1 - mn1) + so1 * __expf(mo1 - mn1);
            m1 = mn1;
        }
        if (lane == 0) {
            red_m[warp][2 * j]     = m0;  red_s[warp][2 * j]     = s0;
            red_m[warp][2 * j + 1] = m1;  red_s[warp][2 * j + 1] = s1;
        }
    }
    __syncthreads();

    // combine the 4 warps of each bg half; tid 0..63 -> (bg2, batch-within)
    if (tid < 64) {
        int bg2 = tid >> 5, bb = tid & 31;
        int w0 = bg2 * 4;
        float M = red_m[w0][bb], S = red_s[w0][bb];
#pragma unroll
        for (int w = 1; w < 4; w++) {
            float m2 = red_m[w0 + w][bb], s2 = red_s[w0 + w][bb];
            float mn = fmaxf(M, m2);
            S = S * __expf(M - mn) + s2 * __expf(m2 - mn);
            M = mn;
        }
        int b = bg2 * 32 + bb;
        g_pm[b * 256 + blockIdx.x] = M;
        g_ps[b * 256 + blockIdx.x] = S;
    }
}

// ---------------------------------------------------------------------------
// Kernel 4: combine 196 partials per batch -> g_lse. grid(64), 32 threads.
// ---------------------------------------------------------------------------
__global__ void lse_combine_kernel() {
    int b = blockIdx.x, lane = threadIdx.x;
    float M = -1e30f, S = 0.f;
    for (int k = lane; k < NLBLK; k += 32) {
        float m2 = g_pm[b * 256 + k], s2 = g_ps[b * 256 + k];
        float mn = fmaxf(M, m2);
        S = S * __expf(M - mn) + s2 * __expf(m2 - mn);
        M = mn;
    }
#pragma unroll
    for (int o = 16; o > 0; o >>= 1) {
        float m2 = __shfl_down_sync(0xffffffffu, M, o);
        float s2 = __shfl_down_sync(0xffffffffu, S, o);
        float mn = fmaxf(M, m2);
        S = S * __expf(M - mn) + s2 * __expf(m2 - mn);
        M = mn;
    }
    if (lane == 0) g_lse[b] = M + logf(S);
}

// ---------------------------------------------------------------------------
// Kernel 5: out[b][v] -= lse[b]  (float4)
// ---------------------------------------------------------------------------
__global__ void norm_kernel(float* __restrict__ out) {
    int i = blockIdx.x * blockDim.x + threadIdx.x;
    const int N4 = BATCH * VOCAB / 4;
    if (i >= N4) return;
    int b = i / (VOCAB / 4);
    float l = g_lse[b];
    float4 v = ((float4*)out)[i];
    v.x -= l; v.y -= l; v.z -= l; v.w -= l;
    ((float4*)out)[i] = v;
}

// ---------------------------------------------------------------------------
extern "C" void kernel_launch(void* const* d_in, const int* in_sizes, int n_in,
                              void* d_out, int out_size) {
    const float* A  = (const float*)d_in[0];
    const float* TA = (const float*)d_in[1];
    const float* TC = (const float*)d_in[2];
    const int*   x  = (const int*)d_in[3];
    const int*   q  = (const int*)d_in[4];
    float* out = (float*)d_out;

    embed_kernel<<<6408, 256>>>(A, x, q);
    hops_kernel<<<64, 256>>>(TA, TC);
    logits_kernel<<<NLBLK, 256>>>(A, out);
    lse_combine_kernel<<<64, 32>>>();
    norm_kernel<<<3125, 256>>>(out);
}

// round 5
// speedup vs baseline: 1.0260x; 1.0260x over previous
#include <cuda_runtime.h>
#include <cstddef>

#define VOCAB 50000
#define EMBD  128
#define STORY 200
#define SENT  32
#define BATCH 64
#define QLEN  32
#define HOPS  3
#define NLBLK 196   // logits blocks = ceil(50000/256)

// Scratch (device globals — no allocation allowed)
__device__ float g_emb[4 * BATCH * STORY * EMBD];  // 26.2 MB: emb[k][b][s][e]
__device__ float g_u[BATCH * EMBD];
__device__ float g_pm[BATCH * 256];   // per-(batch, logits-block) partial max
__device__ float g_ps[BATCH * 256];   // per-(batch, logits-block) partial sum

// ---------------------------------------------------------------------------
// Kernel 1: embedding gather-sums (L2-roofline bound).
// ---------------------------------------------------------------------------
__global__ void embed_kernel(const float* __restrict__ A,
                             const int* __restrict__ x,
                             const int* __restrict__ q) {
    const int NEMB = 4 * BATCH * STORY;  // 51200
    int w    = threadIdx.x >> 5;
    int lane = threadIdx.x & 31;
    int row  = blockIdx.x * 8 + w;

    __shared__ int toks[8][SENT];

    const int*   tokptr;
    const float* table;
    float*       out;

    if (row < NEMB) {
        int k   = row / (BATCH * STORY);
        int rem = row % (BATCH * STORY);
        tokptr = x + rem * SENT;
        table  = A + (size_t)k * VOCAB * EMBD;
        out    = g_emb + (size_t)row * EMBD;
    } else if (row < NEMB + BATCH) {
        int b  = row - NEMB;
        tokptr = q + b * QLEN;
        table  = A + (size_t)1 * VOCAB * EMBD;
        out    = g_u + b * EMBD;
    } else {
        return;
    }

    toks[w][lane] = tokptr[lane];
    __syncwarp();

    float4 acc0 = make_float4(0.f, 0.f, 0.f, 0.f);
    float4 acc1 = make_float4(0.f, 0.f, 0.f, 0.f);
#pragma unroll 8
    for (int t = 0; t < SENT; t += 2) {
        const float4* r0 = (const float4*)(table + (size_t)toks[w][t] * EMBD);
        const float4* r1 = (const float4*)(table + (size_t)toks[w][t + 1] * EMBD);
        float4 v0 = __ldg(&r0[lane]);
        float4 v1 = __ldg(&r1[lane]);
        acc0.x += v0.x; acc0.y += v0.y; acc0.z += v0.z; acc0.w += v0.w;
        acc1.x += v1.x; acc1.y += v1.y; acc1.z += v1.z; acc1.w += v1.w;
    }
    acc0.x += acc1.x; acc0.y += acc1.y; acc0.z += acc1.z; acc0.w += acc1.w;
    ((float4*)out)[lane] = acc0;
}

// ---------------------------------------------------------------------------
// Kernel 2: 3 attention hops (unchanged).
// ---------------------------------------------------------------------------
__global__ void hops_kernel(const float* __restrict__ TA,
                            const float* __restrict__ TC) {
    int b   = blockIdx.x;
    int tid = threadIdx.x;
    int warp = tid >> 5, lane = tid & 31;

    __shared__ float su[EMBD];
    __shared__ float sc[STORY];
    __shared__ float wsum[2][EMBD];
    __shared__ float sred[8];
    __shared__ float s_scalar[4];

    if (tid < EMBD) su[tid] = g_u[b * EMBD + tid];
    __syncthreads();

    for (int k = 0; k < HOPS; k++) {
        if (tid < EMBD) {
            float v = su[tid];
            for (int o = 16; o > 0; o >>= 1) v += __shfl_down_sync(0xffffffffu, v, o);
            if (lane == 0) sred[warp] = v;
        }
        __syncthreads();
        if (tid == 0) s_scalar[0] = sred[0] + sred[1] + sred[2] + sred[3];
        __syncthreads();
        float sum_u = s_scalar[0];

        float4 uv = ((const float4*)su)[lane];
        const float4* embk = (const float4*)(g_emb +
            ((size_t)k * BATCH * STORY + (size_t)b * STORY) * EMBD);
        for (int s = warp; s < STORY; s += 8) {
            float4 m4 = embk[s * 32 + lane];
            float d = m4.x * uv.x + m4.y * uv.y + m4.z * uv.z + m4.w * uv.w;
            for (int o = 16; o > 0; o >>= 1) d += __shfl_down_sync(0xffffffffu, d, o);
            if (lane == 0) sc[s] = d + TA[s] * sum_u;
        }
        __syncthreads();

        if (warp == 0) {
            float m = -1e30f;
            for (int s = lane; s < STORY; s += 32) m = fmaxf(m, sc[s]);
            for (int o = 16; o > 0; o >>= 1) m = fmaxf(m, __shfl_down_sync(0xffffffffu, m, o));
            if (lane == 0) s_scalar[1] = m;
        }
        __syncthreads();
        float smax = s_scalar[1];
        if (tid < STORY) sc[tid] = __expf(sc[tid] - smax);
        __syncthreads();
        if (warp == 0) {
            float sm = 0.f, td = 0.f;
            for (int s = lane; s < STORY; s += 32) { sm += sc[s]; td += sc[s] * TC[s]; }
            for (int o = 16; o > 0; o >>= 1) {
                sm += __shfl_down_sync(0xffffffffu, sm, o);
                td += __shfl_down_sync(0xffffffffu, td, o);
            }
            if (lane == 0) { s_scalar[2] = sm; s_scalar[3] = td; }
        }
        __syncthreads();

        int e = tid & 127, part = tid >> 7;
        const float* embc = g_emb +
            ((size_t)(k + 1) * BATCH * STORY + (size_t)b * STORY) * EMBD;
        float acc = 0.f;
        int s0 = part * 100;
#pragma unroll 4
        for (int s = s0; s < s0 + 100; s++) acc += embc[s * EMBD + e] * sc[s];
        wsum[part][e] = acc;
        __syncthreads();
        if (tid < EMBD) {
            float inv = 1.0f / s_scalar[2];
            su[tid] = su[tid] + (wsum[0][tid] + wsum[1][tid] + s_scalar[3]) * inv;
        }
        __syncthreads();
    }
    if (tid < EMBD) g_u[b * EMBD + tid] = su[tid];
}

// ---------------------------------------------------------------------------
// Kernel 3: logits (packed fma.rn.f32x2, broadcast-u) + cheap fused LSE
// partials (max-then-sum: 64 exps/thread, butterfly shuffles).
// ---------------------------------------------------------------------------
__device__ __forceinline__ unsigned long long fma2(unsigned long long a,
                                                   unsigned long long b,
                                                   unsigned long long c) {
    unsigned long long d;
    asm("fma.rn.f32x2 %0, %1, %2, %3;" : "=l"(d) : "l"(a), "l"(b), "l"(c));
    return d;
}
__device__ __forceinline__ unsigned long long pack2(float x) {
    unsigned long long d;
    asm("mov.b64 %0, {%1, %1};" : "=l"(d) : "f"(x));
    return d;
}
__device__ __forceinline__ float lo32(unsigned long long a) {
    return __uint_as_float((unsigned)(a & 0xffffffffull));
}
__device__ __forceinline__ float hi32(unsigned long long a) {
    return __uint_as_float((unsigned)(a >> 32));
}

__global__ void __launch_bounds__(256) logits_kernel(const float* __restrict__ A,
                                                     float* __restrict__ out) {
    const float* A3 = A + (size_t)HOPS * VOCAB * EMBD;

    __shared__ float2 up2[32 * EMBD];   // 32 KB
    __shared__ float  As[8 * 256];      // 8 KB
    __shared__ float  red_m[8][32];
    __shared__ float  red_s[8][32];

    int tid = threadIdx.x;
    for (int i = tid; i < 32 * EMBD; i += 256) {
        int p = i >> 7, e = i & 127;
        up2[p * EMBD + e] = make_float2(g_u[(2 * p) * EMBD + e],
                                        g_u[(2 * p + 1) * EMBD + e]);
    }

    int vp = tid & 127;
    int bg = tid >> 7;
    int warp = tid >> 5, lane = tid & 31;
    int vbase = blockIdx.x * 256;

    unsigned long long acc0[16], acc1[16];
#pragma unroll
    for (int j = 0; j < 16; j++) { acc0[j] = 0ull; acc1[j] = 0ull; }

    const unsigned long long* uq =
        (const unsigned long long*)up2 + (size_t)bg * 16 * EMBD;

    for (int c = 0; c < 16; c++) {   // 16 chunks of 8 e
        __syncthreads();
#pragma unroll
        for (int i = 0; i < 2; i++) {
            int f   = tid + i * 256;
            int vl2 = f >> 1;
            int e4  = f & 1;
            int vr  = min(vbase + vl2, VOCAB - 1);
            float4 val = __ldg((const float4*)A3 + (size_t)vr * 32 + c * 2 + e4);
            int eb = e4 * 4;
            As[(eb + 0) * 256 + vl2] = val.x;
            As[(eb + 1) * 256 + vl2] = val.y;
            As[(eb + 2) * 256 + vl2] = val.z;
            As[(eb + 3) * 256 + vl2] = val.w;
        }
        __syncthreads();

#pragma unroll
        for (int e = 0; e < 8; e++) {
            float2 a01 = ((const float2*)(As + e * 256))[vp];
            unsigned long long a0 = pack2(a01.x);
            unsigned long long a1 = pack2(a01.y);
            int ue = c * 8 + e;
#pragma unroll
            for (int j = 0; j < 16; j++) {
                unsigned long long uu = uq[j * EMBD + ue];  // warp-uniform broadcast
                acc0[j] = fma2(a0, uu, acc0[j]);
                acc1[j] = fma2(a1, uu, acc1[j]);
            }
        }
    }

    int v0 = vbase + 2 * vp;
    bool ok0 = (v0 < VOCAB);
    bool ok1 = (v0 + 1 < VOCAB);

    // store raw logits
    if (ok0) {
#pragma unroll
        for (int j = 0; j < 16; j++) {
            int b = bg * 32 + 2 * j;
            float2 r0 = make_float2(lo32(acc0[j]), lo32(acc1[j]));
            float2 r1 = make_float2(hi32(acc0[j]), hi32(acc1[j]));
            *(float2*)(out + (size_t)b * VOCAB + v0)       = r0;
            *(float2*)(out + (size_t)(b + 1) * VOCAB + v0) = r1;
        }
    }

    // ---- fused LSE partials: max first (no exp), then one exp pass ----
#pragma unroll
    for (int j = 0; j < 16; j++) {
        float a0 = lo32(acc0[j]), c0 = lo32(acc1[j]);  // batch 2j
        float a1 = hi32(acc0[j]), c1 = hi32(acc1[j]);  // batch 2j+1
        float m0 = fmaxf(ok0 ? a0 : -1e30f, ok1 ? c0 : -1e30f);
        float m1 = fmaxf(ok0 ? a1 : -1e30f, ok1 ? c1 : -1e30f);
#pragma unroll
        for (int o = 16; o > 0; o >>= 1) {
            m0 = fmaxf(m0, __shfl_xor_sync(0xffffffffu, m0, o));
            m1 = fmaxf(m1, __shfl_xor_sync(0xffffffffu, m1, o));
        }
        float s0 = (ok0 ? __expf(a0 - m0) : 0.f) + (ok1 ? __expf(c0 - m0) : 0.f);
        float s1 = (ok0 ? __expf(a1 - m1) : 0.f) + (ok1 ? __expf(c1 - m1) : 0.f);
#pragma unroll
        for (int o = 16; o > 0; o >>= 1) {
            s0 += __shfl_xor_sync(0xffffffffu, s0, o);
            s1 += __shfl_xor_sync(0xffffffffu, s1, o);
        }
        if (lane == 0) {
            red_m[warp][2 * j]     = m0;  red_s[warp][2 * j]     = s0;
            red_m[warp][2 * j + 1] = m1;  red_s[warp][2 * j + 1] = s1;
        }
    }
    __syncthreads();

    // combine the 4 warps of each bg half; tid 0..63 -> (bg2, batch-within)
    if (tid < 64) {
        int bg2 = tid >> 5, bb = tid & 31;
        int w0 = bg2 * 4;
        float M = red_m[w0][bb], S = red_s[w0][bb];
#pragma unroll
        for (int w = 1; w < 4; w++) {
            float m2 = red_m[w0 + w][bb], s2 = red_s[w0 + w][bb];
            float mn = fmaxf(M, m2);
            S = S * __expf(M - mn) + s2 * __expf(m2 - mn);
            M = mn;
        }
        int b = bg2 * 32 + bb;
        g_pm[b * 256 + blockIdx.x] = M;
        g_ps[b * 256 + blockIdx.x] = S;
    }
}

// ---------------------------------------------------------------------------
// Kernel 4: fused LSE-combine + normalize. grid (3 chunks, 64 batches), 1024t.
// Each block folds its batch's 196 partials (redundantly, L2-resident, hidden
// behind other blocks' streaming), then subtracts over its third of the row.
// ---------------------------------------------------------------------------
__global__ void __launch_bounds__(1024) norm_kernel(float* __restrict__ out) {
    int b     = blockIdx.y;
    int chunk = blockIdx.x;
    int tid  = threadIdx.x;
    int lane = tid & 31, warp = tid >> 5;

    __shared__ float wm[8], ws[8];
    __shared__ float s_lse;

    if (tid < 224) {  // 7 full warps cover 196 partials
        float M = -1e30f, S = 0.f;
        if (tid < NLBLK) { M = g_pm[b * 256 + tid]; S = g_ps[b * 256 + tid]; }
#pragma unroll
        for (int o = 16; o > 0; o >>= 1) {
            float m2 = __shfl_xor_sync(0xffffffffu, M, o);
            float s2 = __shfl_xor_sync(0xffffffffu, S, o);
            float mn = fmaxf(M, m2);
            S = S * __expf(M - mn) + s2 * __expf(m2 - mn);
            M = mn;
        }
        if (lane == 0) { wm[warp] = M; ws[warp] = S; }
    }
    __syncthreads();
    if (tid == 0) {
        float M = wm[0], S = ws[0];
#pragma unroll
        for (int w = 1; w < 7; w++) {
            float mn = fmaxf(M, wm[w]);
            S = S * __expf(M - mn) + ws[w] * __expf(wm[w] - mn);
            M = mn;
        }
        s_lse = M + logf(S);
    }
    __syncthreads();
    float l = s_lse;

    const int N4 = VOCAB / 4;          // 12500
    const int per = (N4 + 2) / 3;      // 4167
    int start = chunk * per;
    int end   = min(start + per, N4);
    float4* row = (float4*)(out + (size_t)b * VOCAB);
    for (int i = start + tid; i < end; i += 1024) {
        float4 v = row[i];
        v.x -= l; v.y -= l; v.z -= l; v.w -= l;
        row[i] = v;
    }
}

// ---------------------------------------------------------------------------
extern "C" void kernel_launch(void* const* d_in, const int* in_sizes, int n_in,
                              void* d_out, int out_size) {
    const float* A  = (const float*)d_in[0];
    const float* TA = (const float*)d_in[1];
    const float* TC = (const float*)d_in[2];
    const int*   x  = (const int*)d_in[3];
    const int*   q  = (const int*)d_in[4];
    float* out = (float*)d_out;

    embed_kernel<<<6408, 256>>>(A, x, q);
    hops_kernel<<<64, 256>>>(TA, TC);
    logits_kernel<<<NLBLK, 256>>>(A, out);
    norm_kernel<<<dim3(3, 64), 1024>>>(out);
}